// round 13
// baseline (speedup 1.0000x reference)
#include <cuda_runtime.h>
#include <stdint.h>

#define HOPS   3
#define LBL    10
#define DIM    128
#define ROWB   512                    // bytes per node row (128 f32)
#define WPB    10                     // one consumer warp per label
#define THREADS (WPB * 32)
#define WIN    32                     // nodes per window
#define PF_AHEAD 6                    // windows of prefetch lead (96 KB/CTA)
#define GRIDX  196                    // per hop; 196*3=588 ~ 148 SMs * 4 CTA/SM

// Scratch (__device__ globals — zero-initialized at load; finalizer re-zeroes
// them each run so every graph replay starts from clean scratch).
__device__ float        g_sums[HOPS * LBL * DIM];
__device__ float        g_counts[LBL];
__device__ unsigned int g_done;

// Bulk L2 prefetch hint: fetches [ptr, ptr+bytes) into L2 via the bulk engine.
__device__ __forceinline__ void prefetch_l2(const void* ptr, uint32_t bytes) {
    asm volatile("cp.async.bulk.prefetch.L2.global [%0], %1;"
                 :: "l"(ptr), "r"(bytes) : "memory");
}

// ---------------------------------------------------------------------------
// Hot loop: warp = one label. Per 32-node window: read 32 labels (1 line,
// L1-hit for 9/10 warps), ballot matches, batch up to 4 row loads (LDG.128,
// L2-hit thanks to the prefetch stream) into 4-register accumulators.
// Warp 0 lane 0 additionally issues the L2 prefetch for window +PF_AHEAD.
// ---------------------------------------------------------------------------
template <bool IS64>
__device__ __forceinline__ void hot_loop(const float4* __restrict__ e4,
                                         const void*   __restrict__ labels_raw,
                                         int mylabel, int N, int lane, int warp,
                                         int firstWin, int winStride,
                                         float& ax, float& ay, float& az, float& aw,
                                         int& mycount) {
    const int*       l32 = reinterpret_cast<const int*>(labels_raw);
    const long long* l64 = reinterpret_cast<const long long*>(labels_raw);

    for (int wbase = firstWin; wbase < N; wbase += winStride) {
        // Self-paced L2 prefetch: one issue per consumed window, 6 ahead.
        if (warp == 0 && lane == 0) {
            long long pf = (long long)wbase + (long long)PF_AHEAD * winStride;
            if (pf < N) {
                int rows = N - (int)pf; if (rows > WIN) rows = WIN;
                prefetch_l2(reinterpret_cast<const char*>(e4) + pf * (long long)ROWB,
                            (uint32_t)rows * ROWB);
            }
        }

        int n = wbase + lane;
        int lab = -1;
        if (n < N) lab = IS64 ? (int)l64[n] : l32[n];

        unsigned mask = __ballot_sync(0xffffffffu, lab == mylabel);
        mycount += __popc(mask);

        while (mask) {
            int idx[4];
#pragma unroll
            for (int k = 0; k < 4; k++) {
                if (mask) { int idxv = __ffs(mask) - 1; mask &= mask - 1; idx[k] = idxv; }
                else idx[k] = -1;
            }
            float4 v[4];
#pragma unroll
            for (int k = 0; k < 4; k++)
                if (idx[k] >= 0)
                    v[k] = e4[(size_t)(wbase + idx[k]) * (DIM / 4) + lane];
#pragma unroll
            for (int k = 0; k < 4; k++)
                if (idx[k] >= 0) {
                    ax += v[k].x; ay += v[k].y; az += v[k].z; aw += v[k].w;
                }
        }
    }
}

// ---------------------------------------------------------------------------
// Single fused kernel. blockIdx.y = hop. Last block (global ticket) finalizes
// the output and re-zeroes scratch for the next graph replay.
// ---------------------------------------------------------------------------
__global__ void __launch_bounds__(THREADS, 4)
accumulate_kernel(const float* __restrict__ emb,
                  const void*  __restrict__ labels_raw,
                  int N,
                  const float* __restrict__ weight,
                  float* __restrict__ out,
                  int totalBlocks) {
    __shared__ int s_not64;
    __shared__ unsigned int s_ticket;

    const int tid  = threadIdx.x;
    const int warp = tid >> 5;     // == label for this warp
    const int lane = tid & 31;
    const int hop  = blockIdx.y;

    if (tid == 0) s_not64 = 0;
    __syncthreads();

    // labels dtype detection: int64 labels (0..9, LE) => odd 32-bit words all 0.
    {
        const int* l32 = reinterpret_cast<const int*>(labels_raw);
        int nscan = N / 2; if (nscan > 4096) nscan = 4096;
        for (int j = tid; j < nscan; j += THREADS)
            if (l32[2 * j + 1] != 0) s_not64 = 1;
    }
    __syncthreads();
    const bool is64 = (s_not64 == 0);

    const float4* e4 = reinterpret_cast<const float4*>(emb) + (size_t)hop * N * (DIM / 4);

    float ax = 0.0f, ay = 0.0f, az = 0.0f, aw = 0.0f;
    int mycount = 0;

    const int firstWin  = blockIdx.x * WIN;
    const int winStride = gridDim.x * WIN;

    if (is64) hot_loop<true >(e4, labels_raw, warp, N, lane, warp, firstWin, winStride,
                              ax, ay, az, aw, mycount);
    else      hot_loop<false>(e4, labels_raw, warp, N, lane, warp, firstWin, winStride,
                              ax, ay, az, aw, mycount);

    // Epilogue: spread REDG (each address hit by GRIDX blocks).
    {
        float* dst = &g_sums[hop * LBL * DIM + warp * DIM + lane * 4];
        atomicAdd(dst + 0, ax);
        atomicAdd(dst + 1, ay);
        atomicAdd(dst + 2, az);
        atomicAdd(dst + 3, aw);
    }
    if (hop == 0 && lane == 0 && mycount != 0)
        atomicAdd(&g_counts[warp], (float)mycount);

    // Last-block ticket -> finalize + scratch reset.
    __threadfence();
    __syncthreads();
    if (tid == 0) s_ticket = atomicAdd(&g_done, 1u);
    __syncthreads();
    if (s_ticket == (unsigned int)(totalBlocks - 1)) {
        for (int i = tid; i < HOPS * LBL * DIM; i += THREADS) {
            int l = (i / DIM) % LBL;
            float c = __ldcg(&g_counts[l]);
            if (c < 1.0f) c = 1.0f;
            out[i] = __ldcg(&g_sums[i]) / c + weight[i];
            g_sums[i] = 0.0f;                       // self-clean for next replay
        }
        if (tid < LBL) {
            out[HOPS * LBL * DIM + tid] = __ldcg(&g_counts[tid]);
            g_counts[tid] = 0.0f;
        }
        __syncthreads();
        if (tid == 0) g_done = 0u;                  // reset ticket last
    }
}

// ---------------------------------------------------------------------------
extern "C" void kernel_launch(void* const* d_in, const int* in_sizes, int n_in,
                              void* d_out, int out_size) {
    const float* emb    = (const float*)d_in[0];   // [3, N, 128] f32
    const void*  labels = d_in[1];                 // [N] int32 or int64
    const float* weight = (const float*)d_in[2];   // [3, 10, 128] f32
    float*       out    = (float*)d_out;           // 3850 f32

    const int N = in_sizes[1];

    dim3 grid(GRIDX, HOPS, 1);
    accumulate_kernel<<<grid, THREADS>>>(emb, labels, N, weight, out,
                                         GRIDX * HOPS);
}

// round 14
// speedup vs baseline: 1.2863x; 1.2863x over previous
#include <cuda_runtime.h>
#include <stdint.h>

#define HOPS   3
#define LBL    10
#define DIM    128
#define ROWB   512                      // bytes per node row (128 f32)
#define CHUNK  32                       // nodes per pipeline stage (16 KB)
#define STAGES 6
#define STAGE_BYTES (CHUNK * ROWB)
#define SMEM_STAGE0 1024
#define SMEM_TOTAL  (SMEM_STAGE0 + STAGES * STAGE_BYTES)   // 99328 B -> 2 CTA/SM
#define WARPS  11                       // 10 consumers (1/label) + 1 producer
#define THREADS (WARPS * 32)
#define GRIDX  98                       // per hop; 98*3=294 CTAs = one wave @2 CTA/SM

// Scratch (__device__ globals — zero-initialized at load; finalizer re-zeroes
// them each run so every graph replay starts from clean scratch).
__device__ float        g_sums[HOPS * LBL * DIM];
__device__ float        g_counts[LBL];
__device__ unsigned int g_done;

// --- PTX helpers -----------------------------------------------------------
__device__ __forceinline__ uint32_t smem_u32(const void* p) {
    uint32_t a;
    asm("{ .reg .u64 t; cvta.to.shared.u64 t, %1; cvt.u32.u64 %0, t; }"
        : "=r"(a) : "l"(p));
    return a;
}
#define MBAR_INIT(addr, cnt) \
    asm volatile("mbarrier.init.shared.b64 [%0], %1;" :: "r"(addr), "r"(cnt) : "memory")
#define MBAR_EXPECT_TX(addr, bytes) \
    asm volatile("mbarrier.arrive.expect_tx.shared.b64 _, [%0], %1;" :: "r"(addr), "r"(bytes) : "memory")
#define MBAR_ARRIVE(addr) \
    asm volatile("mbarrier.arrive.shared.b64 _, [%0];" :: "r"(addr) : "memory")
#define MBAR_WAIT(addr, parity) do {                                          \
    uint32_t _m = (addr); uint32_t _p = (parity); uint32_t _d;                \
    asm volatile("{ .reg .pred p;\n\t"                                        \
        "mbarrier.try_wait.parity.acquire.cta.shared::cta.b64 p, [%1], %2;\n\t"\
        "selp.b32 %0, 1, 0, p; }" : "=r"(_d) : "r"(_m), "r"(_p) : "memory");  \
    if (!_d) {                                                                \
        asm volatile("{ .reg .pred P1;\n\t"                                   \
            "W%=:\n\t"                                                        \
            "mbarrier.try_wait.parity.acquire.cta.shared::cta.b64 P1, [%0], %1, 0x989680;\n\t" \
            "@P1 bra.uni D%=;\n\t"                                            \
            "bra.uni W%=;\n\t"                                                \
            "D%=: }" :: "r"(_m), "r"(_p) : "memory");                         \
    }                                                                         \
} while (0)
// 1D bulk copy global->shared (SASS: UBLKCP), complete_tx to mbarrier.
#define BULK_G2S(dst, src, bytes, mbar) \
    asm volatile("cp.async.bulk.shared::cluster.global.mbarrier::complete_tx::bytes [%0], [%1], %2, [%3];" \
        :: "r"(dst), "l"(src), "r"(bytes), "r"(mbar) : "memory")

__device__ __forceinline__ void lds128(uint32_t a, float& x, float& y, float& z, float& w) {
    asm volatile("ld.shared.v4.f32 {%0,%1,%2,%3}, [%4];"
                 : "=f"(x), "=f"(y), "=f"(z), "=f"(w) : "r"(a));
}

// Consume all set bits of mask: batched LDS.128 row reads + register FADD.
__device__ __forceinline__ void eat_mask(unsigned mask, uint32_t rowbase, int lane,
                                         float& ax, float& ay, float& az, float& aw) {
    while (mask) {
        uint32_t a[4]; int nb = 0;
#pragma unroll
        for (int k = 0; k < 4; k++) {
            if (mask) { int idx = __ffs(mask) - 1; mask &= mask - 1;
                        a[k] = rowbase + idx * ROWB + lane * 16; nb = k + 1; }
        }
        float x[4], y[4], z[4], w[4];
#pragma unroll
        for (int k = 0; k < 4; k++) if (k < nb) lds128(a[k], x[k], y[k], z[k], w[k]);
#pragma unroll
        for (int k = 0; k < 4; k++) if (k < nb) { ax += x[k]; ay += y[k]; az += z[k]; aw += w[k]; }
    }
}

// ---------------------------------------------------------------------------
// Single fused kernel. blockIdx.y = hop. Warp 10 = producer (cp.async.bulk
// ring, 6 stages x 16 KB, 2 CTA/SM). Warps 0-9 = per-label consumers.
// Last block (global ticket) finalizes output and re-zeroes scratch.
// ---------------------------------------------------------------------------
__global__ void __launch_bounds__(THREADS, 2)
accumulate_kernel(const float* __restrict__ emb,
                  const void*  __restrict__ labels_raw,
                  int N,
                  const float* __restrict__ weight,
                  float* __restrict__ out,
                  int totalBlocks) {
    extern __shared__ char smem[];
    const uint32_t sb = smem_u32(smem);
    __shared__ int s_not64;
    __shared__ unsigned int s_ticket;

    const int tid  = threadIdx.x;
    const int warp = tid >> 5;
    const int lane = tid & 31;
    const int hop  = blockIdx.y;

    // mbarriers: full(s)=sb+s*16, empty(s)=sb+s*16+8
    if (tid == 0) {
        for (int s = 0; s < STAGES; s++) {
            MBAR_INIT(sb + s * 16,     1u);    // full: tx-based
            MBAR_INIT(sb + s * 16 + 8, 10u);   // empty: 10 consumer warps
        }
        s_not64 = 0;
    }
    __syncthreads();

    // labels dtype detection: int64 labels (0..9, LE) => odd 32-bit words all 0.
    {
        const int* l32 = reinterpret_cast<const int*>(labels_raw);
        int nscan = N / 2; if (nscan > 4096) nscan = 4096;
        for (int j = tid; j < nscan; j += THREADS)
            if (l32[2 * j + 1] != 0) s_not64 = 1;
    }
    __syncthreads();
    const bool is64 = (s_not64 == 0);

    const int CHUNKS = (N + CHUNK - 1) / CHUNK;

    if (warp == 10) {
        // ---------------- producer ----------------
        if (lane == 0) {
            int stage = 0, phase = 1;   // first STAGES empty-waits pass immediately
            const char* hop_base = reinterpret_cast<const char*>(emb)
                                   + (size_t)hop * N * ROWB;
            for (int c = blockIdx.x; c < CHUNKS; c += gridDim.x) {
                MBAR_WAIT(sb + stage * 16 + 8, phase);
                int base = c * CHUNK;
                int rows = N - base; if (rows > CHUNK) rows = CHUNK;
                uint32_t bytes = (uint32_t)rows * ROWB;
                MBAR_EXPECT_TX(sb + stage * 16, bytes);
                BULK_G2S(sb + SMEM_STAGE0 + stage * STAGE_BYTES,
                         hop_base + (size_t)base * ROWB, bytes, sb + stage * 16);
                if (++stage == STAGES) { stage = 0; phase ^= 1; }
            }
        }
    } else {
        // ---------------- consumers (one label per warp) ----------------
        const int mylabel = warp;
        const int*       l32 = reinterpret_cast<const int*>(labels_raw);
        const long long* l64 = reinterpret_cast<const long long*>(labels_raw);
        float ax = 0.f, ay = 0.f, az = 0.f, aw = 0.f;
        int cnt = 0;
        int stage = 0, phase = 0;

        for (int c = blockIdx.x; c < CHUNKS; c += gridDim.x) {
            int base = c * CHUNK;
            int rows = N - base; if (rows > CHUNK) rows = CHUNK;

            // labels from global (L1-hit for 9/10 warps) — overlap the bulk copy
            int lab = -1;
            if (lane < rows)
                lab = is64 ? (int)l64[base + lane] : l32[base + lane];
            unsigned m = __ballot_sync(0xffffffffu, lab == mylabel);
            cnt += __popc(m);

            MBAR_WAIT(sb + stage * 16, phase);
            eat_mask(m, sb + SMEM_STAGE0 + stage * STAGE_BYTES, lane, ax, ay, az, aw);
            __syncwarp();
            if (lane == 0) MBAR_ARRIVE(sb + stage * 16 + 8);
            if (++stage == STAGES) { stage = 0; phase ^= 1; }
        }

        // epilogue: spread REDG (each address hit by GRIDX blocks)
        float* dst = &g_sums[hop * LBL * DIM + mylabel * DIM + lane * 4];
        atomicAdd(dst + 0, ax);
        atomicAdd(dst + 1, ay);
        atomicAdd(dst + 2, az);
        atomicAdd(dst + 3, aw);
        if (hop == 0 && lane == 0 && cnt != 0)
            atomicAdd(&g_counts[mylabel], (float)cnt);
    }

    // ---------------- last-block ticket -> finalize + scratch reset ----------
    __threadfence();
    __syncthreads();
    if (tid == 0) s_ticket = atomicAdd(&g_done, 1u);
    __syncthreads();
    if (s_ticket == (unsigned int)(totalBlocks - 1)) {
        for (int i = tid; i < HOPS * LBL * DIM; i += THREADS) {
            int l = (i / DIM) % LBL;
            float c = __ldcg(&g_counts[l]);
            if (c < 1.0f) c = 1.0f;
            out[i] = __ldcg(&g_sums[i]) / c + weight[i];
            g_sums[i] = 0.0f;                       // self-clean for next replay
        }
        if (tid < LBL) {
            out[HOPS * LBL * DIM + tid] = __ldcg(&g_counts[tid]);
            g_counts[tid] = 0.0f;
        }
        __syncthreads();
        if (tid == 0) g_done = 0u;                  // reset ticket last
    }
}

// ---------------------------------------------------------------------------
extern "C" void kernel_launch(void* const* d_in, const int* in_sizes, int n_in,
                              void* d_out, int out_size) {
    const float* emb    = (const float*)d_in[0];   // [3, N, 128] f32
    const void*  labels = d_in[1];                 // [N] int32 or int64
    const float* weight = (const float*)d_in[2];   // [3, 10, 128] f32
    float*       out    = (float*)d_out;           // 3850 f32

    const int N = in_sizes[1];

    static bool attr_set = false;
    if (!attr_set) {
        cudaFuncSetAttribute(accumulate_kernel,
                             cudaFuncAttributeMaxDynamicSharedMemorySize, SMEM_TOTAL);
        attr_set = true;
    }

    dim3 grid(GRIDX, HOPS, 1);
    accumulate_kernel<<<grid, THREADS, SMEM_TOTAL>>>(emb, labels, N, weight, out,
                                                     GRIDX * HOPS);
}

// round 15
// speedup vs baseline: 1.3722x; 1.0668x over previous
#include <cuda_runtime.h>
#include <stdint.h>

#define HOPS   3
#define LBL    10
#define DIM    128
#define ROWB   512                      // bytes per node row (128 f32)
#define CHUNK  64                       // nodes per pipeline stage (32 KB)
#define STAGES 3
#define STAGE_BYTES (CHUNK * ROWB)
#define SMEM_STAGE0 1024
#define SMEM_TOTAL  (SMEM_STAGE0 + STAGES * STAGE_BYTES)   // 99328 B -> 2 CTA/SM
#define WARPS  11                       // 10 consumers (1/label) + 1 producer
#define THREADS (WARPS * 32)
#define GRIDX  98                       // per hop; 98*3=294 CTAs = one wave @2 CTA/SM

// Scratch (__device__ globals — zero-initialized at load; the finalizer
// re-zeroes them each run so every graph replay starts from clean scratch).
__device__ float        g_sums[HOPS * LBL * DIM];
__device__ float        g_counts[LBL];
__device__ unsigned int g_done;

// --- PTX helpers -----------------------------------------------------------
__device__ __forceinline__ uint32_t smem_u32(const void* p) {
    uint32_t a;
    asm("{ .reg .u64 t; cvta.to.shared.u64 t, %1; cvt.u32.u64 %0, t; }"
        : "=r"(a) : "l"(p));
    return a;
}
#define MBAR_INIT(addr, cnt) \
    asm volatile("mbarrier.init.shared.b64 [%0], %1;" :: "r"(addr), "r"(cnt) : "memory")
#define MBAR_EXPECT_TX(addr, bytes) \
    asm volatile("mbarrier.arrive.expect_tx.shared.b64 _, [%0], %1;" :: "r"(addr), "r"(bytes) : "memory")
#define MBAR_ARRIVE(addr) \
    asm volatile("mbarrier.arrive.shared.b64 _, [%0];" :: "r"(addr) : "memory")
#define MBAR_WAIT(addr, parity) do {                                          \
    uint32_t _m = (addr); uint32_t _p = (parity); uint32_t _d;                \
    asm volatile("{ .reg .pred p;\n\t"                                        \
        "mbarrier.try_wait.parity.acquire.cta.shared::cta.b64 p, [%1], %2;\n\t"\
        "selp.b32 %0, 1, 0, p; }" : "=r"(_d) : "r"(_m), "r"(_p) : "memory");  \
    if (!_d) {                                                                \
        asm volatile("{ .reg .pred P1;\n\t"                                   \
            "W%=:\n\t"                                                        \
            "mbarrier.try_wait.parity.acquire.cta.shared::cta.b64 P1, [%0], %1, 0x989680;\n\t" \
            "@P1 bra.uni D%=;\n\t"                                            \
            "bra.uni W%=;\n\t"                                                \
            "D%=: }" :: "r"(_m), "r"(_p) : "memory");                         \
    }                                                                         \
} while (0)
// 1D bulk copy global->shared (SASS: UBLKCP), complete_tx to mbarrier.
#define BULK_G2S(dst, src, bytes, mbar) \
    asm volatile("cp.async.bulk.shared::cluster.global.mbarrier::complete_tx::bytes [%0], [%1], %2, [%3];" \
        :: "r"(dst), "l"(src), "r"(bytes), "r"(mbar) : "memory")

__device__ __forceinline__ void lds128(uint32_t a, float& x, float& y, float& z, float& w) {
    asm volatile("ld.shared.v4.f32 {%0,%1,%2,%3}, [%4];"
                 : "=f"(x), "=f"(y), "=f"(z), "=f"(w) : "r"(a));
}

// Consume all set bits of mask: batched LDS.128 row reads + register FADD.
__device__ __forceinline__ void eat_mask(unsigned mask, uint32_t rowbase, int lane,
                                         float& ax, float& ay, float& az, float& aw) {
    while (mask) {
        uint32_t a[4]; int nb = 0;
#pragma unroll
        for (int k = 0; k < 4; k++) {
            if (mask) { int idx = __ffs(mask) - 1; mask &= mask - 1;
                        a[k] = rowbase + idx * ROWB + lane * 16; nb = k + 1; }
        }
        float x[4], y[4], z[4], w[4];
#pragma unroll
        for (int k = 0; k < 4; k++) if (k < nb) lds128(a[k], x[k], y[k], z[k], w[k]);
#pragma unroll
        for (int k = 0; k < 4; k++) if (k < nb) { ax += x[k]; ay += y[k]; az += z[k]; aw += w[k]; }
    }
}

// ---------------------------------------------------------------------------
// Single fused kernel (R10 accumulate config + R12 fusion). blockIdx.y = hop.
// Warp 10 = producer (cp.async.bulk ring, 3 stages x 32 KB, 2 CTA/SM).
// Warps 0-9 = per-label consumers: ballot the chunk's labels (global reads,
// L1-hit for 9/10 warps, overlapping the bulk copy), LDS.128 matching rows,
// register accumulators. Last block (global ticket) finalizes the output and
// re-zeroes scratch for the next graph replay.
// ---------------------------------------------------------------------------
__global__ void __launch_bounds__(THREADS, 2)
accumulate_kernel(const float* __restrict__ emb,
                  const void*  __restrict__ labels_raw,
                  int N,
                  const float* __restrict__ weight,
                  float* __restrict__ out,
                  int totalBlocks) {
    extern __shared__ char smem[];
    const uint32_t sb = smem_u32(smem);
    __shared__ int s_not64;
    __shared__ unsigned int s_ticket;

    const int tid  = threadIdx.x;
    const int warp = tid >> 5;
    const int lane = tid & 31;
    const int hop  = blockIdx.y;

    // mbarriers: full(s)=sb+s*16, empty(s)=sb+s*16+8
    if (tid == 0) {
        for (int s = 0; s < STAGES; s++) {
            MBAR_INIT(sb + s * 16,     1u);    // full: tx-based
            MBAR_INIT(sb + s * 16 + 8, 10u);   // empty: 10 consumer warps
        }
        s_not64 = 0;
    }
    __syncthreads();

    // labels dtype detection: int64 labels (0..9, LE) => odd 32-bit words all 0.
    {
        const int* l32 = reinterpret_cast<const int*>(labels_raw);
        int nscan = N / 2; if (nscan > 4096) nscan = 4096;
        for (int j = tid; j < nscan; j += THREADS)
            if (l32[2 * j + 1] != 0) s_not64 = 1;
    }
    __syncthreads();
    const bool is64 = (s_not64 == 0);

    const int CHUNKS = (N + CHUNK - 1) / CHUNK;

    if (warp == 10) {
        // ---------------- producer ----------------
        if (lane == 0) {
            int stage = 0, phase = 1;   // first STAGES empty-waits pass immediately
            const char* hop_base = reinterpret_cast<const char*>(emb)
                                   + (size_t)hop * N * ROWB;
            for (int c = blockIdx.x; c < CHUNKS; c += gridDim.x) {
                MBAR_WAIT(sb + stage * 16 + 8, phase);
                int base = c * CHUNK;
                int rows = N - base; if (rows > CHUNK) rows = CHUNK;
                uint32_t bytes = (uint32_t)rows * ROWB;
                MBAR_EXPECT_TX(sb + stage * 16, bytes);
                BULK_G2S(sb + SMEM_STAGE0 + stage * STAGE_BYTES,
                         hop_base + (size_t)base * ROWB, bytes, sb + stage * 16);
                if (++stage == STAGES) { stage = 0; phase ^= 1; }
            }
        }
    } else {
        // ---------------- consumers (one label per warp) ----------------
        const int mylabel = warp;
        const int*       l32 = reinterpret_cast<const int*>(labels_raw);
        const long long* l64 = reinterpret_cast<const long long*>(labels_raw);
        float ax = 0.f, ay = 0.f, az = 0.f, aw = 0.f;
        int cnt = 0;
        int stage = 0, phase = 0;

        for (int c = blockIdx.x; c < CHUNKS; c += gridDim.x) {
            int base = c * CHUNK;
            int rows = N - base; if (rows > CHUNK) rows = CHUNK;

            // labels from global (L1-hit for 9/10 warps) — overlap the bulk copy
            int la = -1, lb = -1;
            if (lane < rows)      la = is64 ? (int)l64[base + lane]      : l32[base + lane];
            if (32 + lane < rows) lb = is64 ? (int)l64[base + 32 + lane] : l32[base + 32 + lane];
            unsigned m0 = __ballot_sync(0xffffffffu, la == mylabel);
            unsigned m1 = __ballot_sync(0xffffffffu, lb == mylabel);
            cnt += __popc(m0) + __popc(m1);

            MBAR_WAIT(sb + stage * 16, phase);
            uint32_t sbase = sb + SMEM_STAGE0 + stage * STAGE_BYTES;
            eat_mask(m0, sbase,             lane, ax, ay, az, aw);
            eat_mask(m1, sbase + 32 * ROWB, lane, ax, ay, az, aw);
            __syncwarp();
            if (lane == 0) MBAR_ARRIVE(sb + stage * 16 + 8);
            if (++stage == STAGES) { stage = 0; phase ^= 1; }
        }

        // epilogue: spread REDG (each address hit by GRIDX blocks)
        float* dst = &g_sums[hop * LBL * DIM + mylabel * DIM + lane * 4];
        atomicAdd(dst + 0, ax);
        atomicAdd(dst + 1, ay);
        atomicAdd(dst + 2, az);
        atomicAdd(dst + 3, aw);
        if (hop == 0 && lane == 0 && cnt != 0)
            atomicAdd(&g_counts[mylabel], (float)cnt);
    }

    // ---------------- last-block ticket -> finalize + scratch reset ----------
    __threadfence();
    __syncthreads();
    if (tid == 0) s_ticket = atomicAdd(&g_done, 1u);
    __syncthreads();
    if (s_ticket == (unsigned int)(totalBlocks - 1)) {
        for (int i = tid; i < HOPS * LBL * DIM; i += THREADS) {
            int l = (i / DIM) % LBL;
            float c = __ldcg(&g_counts[l]);
            if (c < 1.0f) c = 1.0f;
            out[i] = __ldcg(&g_sums[i]) / c + weight[i];
            g_sums[i] = 0.0f;                       // self-clean for next replay
        }
        if (tid < LBL) {
            out[HOPS * LBL * DIM + tid] = __ldcg(&g_counts[tid]);
            g_counts[tid] = 0.0f;
        }
        __syncthreads();
        if (tid == 0) g_done = 0u;                  // reset ticket last
    }
}

// ---------------------------------------------------------------------------
extern "C" void kernel_launch(void* const* d_in, const int* in_sizes, int n_in,
                              void* d_out, int out_size) {
    const float* emb    = (const float*)d_in[0];   // [3, N, 128] f32
    const void*  labels = d_in[1];                 // [N] int32 or int64
    const float* weight = (const float*)d_in[2];   // [3, 10, 128] f32
    float*       out    = (float*)d_out;           // 3850 f32

    const int N = in_sizes[1];

    static bool attr_set = false;
    if (!attr_set) {
        cudaFuncSetAttribute(accumulate_kernel,
                             cudaFuncAttributeMaxDynamicSharedMemorySize, SMEM_TOTAL);
        attr_set = true;
    }

    dim3 grid(GRIDX, HOPS, 1);
    accumulate_kernel<<<grid, THREADS, SMEM_TOTAL>>>(emb, labels, N, weight, out,
                                                     GRIDX * HOPS);
}